// round 1
// baseline (speedup 1.0000x reference)
#include <cuda_runtime.h>
#include <cuda_bf16.h>
#include <cstddef>

// SAPA fused kernel, fp32 baseline.
// Shapes: B=4, C=256, E=32, H=W=64, UP=2 (hi 128x128), K=5 (pad 2), GROUPS=32 (8 ch/group).

#define B_      4
#define C_      256
#define E_      32
#define HLO     64
#define WLO     64
#define HHI     128
#define WHI     128
#define NPIX_LO 4096      // 64*64
#define NPIX_HI 16384     // 128*128
#define NGRP    32
#define CPG     8         // channels per group
#define TL      8         // low-res tile side per block
#define HALO    12        // TL + 4
#define EPSF    1e-5f

// -------- device scratch (no allocations allowed) --------
__device__ float g_mu_y[B_ * NGRP];
__device__ float g_rs_y[B_ * NGRP];
__device__ float g_mu_x[B_ * NGRP];
__device__ float g_rs_x[B_ * NGRP];
__device__ float g_k[B_ * E_ * NPIX_LO];   // k features, layout [b][e][64*64]

// ============================================================
// Kernel 1: per-(b,group) mean / rstd.  One block per group.
// Data for a group is contiguous: CPG channels * npix floats.
// ============================================================
__global__ void gn_stats_kernel(const float* __restrict__ in, int n_per_group,
                                float* __restrict__ mu_out, float* __restrict__ rs_out)
{
    int bg  = blockIdx.x;
    int tid = threadIdx.x;
    const float4* p = reinterpret_cast<const float4*>(in + (size_t)bg * n_per_group);
    int n4 = n_per_group >> 2;

    float s = 0.f, ss = 0.f;
    for (int i = tid; i < n4; i += blockDim.x) {
        float4 v = p[i];
        s  += v.x + v.y + v.z + v.w;
        ss += v.x*v.x + v.y*v.y + v.z*v.z + v.w*v.w;
    }

    __shared__ float red_s[256];
    __shared__ float red_ss[256];
    red_s[tid] = s; red_ss[tid] = ss;
    __syncthreads();
    for (int off = 128; off > 0; off >>= 1) {
        if (tid < off) {
            red_s[tid]  += red_s[tid + off];
            red_ss[tid] += red_ss[tid + off];
        }
        __syncthreads();
    }
    if (tid == 0) {
        float inv_n = 1.f / (float)n_per_group;
        float m   = red_s[0] * inv_n;
        float var = red_ss[0] * inv_n - m * m;
        mu_out[bg] = m;
        rs_out[bg] = rsqrtf(var + EPSF);
    }
}

// ============================================================
// Kernel 2: k = k_w @ gn(x) + k_b  (GN folded).  Writes g_k.
// grid (16, 4)  block 256 ; each thread = one low-res pixel.
// ============================================================
__global__ void kproj_kernel(const float* __restrict__ x,
                             const float* __restrict__ k_w,
                             const float* __restrict__ k_b,
                             const float* __restrict__ gn_x_w,
                             const float* __restrict__ gn_x_b)
{
    __shared__ float w_s[C_ * E_];   // [c][e]
    __shared__ float s_s[C_];
    __shared__ float t_s[C_];

    int tid = threadIdx.x;
    int b   = blockIdx.y;

    for (int i = tid; i < C_ * E_; i += 256) {
        int c = i >> 5, e = i & 31;
        w_s[i] = k_w[e * C_ + c];
    }
    {
        int c = tid;                     // blockDim == 256 == C_
        int g = c >> 3;
        float mu = g_mu_x[b * NGRP + g];
        float r  = g_rs_x[b * NGRP + g];
        float sc = r * gn_x_w[c];
        s_s[c] = sc;
        t_s[c] = gn_x_b[c] - mu * sc;
    }
    __syncthreads();

    int pix = blockIdx.x * 256 + tid;
    const float* xp = x + (size_t)b * C_ * NPIX_LO + pix;

    float acc[E_];
#pragma unroll
    for (int e = 0; e < E_; e++) acc[e] = __ldg(&k_b[e]);

#pragma unroll 2
    for (int c = 0; c < C_; c++) {
        float xv = xp[(size_t)c * NPIX_LO];
        float xn = fmaf(xv, s_s[c], t_s[c]);
        const float* wc = &w_s[c << 5];
#pragma unroll
        for (int e = 0; e < E_; e++) acc[e] = fmaf(wc[e], xn, acc[e]);
    }

    float* kp = g_k + (size_t)b * E_ * NPIX_LO + pix;
#pragma unroll
    for (int e = 0; e < E_; e++) kp[(size_t)e * NPIX_LO] = acc[e];
}

// ============================================================
// Kernel 3: fused  q-proj (GN folded) + logits + softmax + aggregation.
// grid (8, 8, 4)  block 256 ; thread = one hi-res pixel of a 16x16 tile.
// Dynamic smem layout (floats):
//   [0     .. 8192)  w_s   (q_w transposed [c][e])   -- reused as x_s in phase e
//   [8192  .. 8448)  sy_s
//   [8448  .. 8704)  ty_s
//   [8704  .. 13312) k_s   [e][12*12] halo tile
// ============================================================
__global__ void sapa_main_kernel(const float* __restrict__ y,
                                 const float* __restrict__ q_w,
                                 const float* __restrict__ q_b,
                                 const float* __restrict__ gn_y_w,
                                 const float* __restrict__ gn_y_b,
                                 const float* __restrict__ x,
                                 float* __restrict__ out)
{
    extern __shared__ float sm[];
    float* w_s  = sm;              // 8192
    float* sy_s = sm + 8192;       // 256
    float* ty_s = sm + 8448;       // 256
    float* k_s  = sm + 8704;       // 32*144 = 4608
    float* x_s  = sm;              // phase e: 144 float4 = 576 floats (over dead w_s)

    int tid  = threadIdx.x;
    int b    = blockIdx.z;
    int th0  = blockIdx.y * TL;    // low-res tile origin
    int tw0  = blockIdx.x * TL;

    // ---- phase a: cooperative loads ----
    for (int i = tid; i < C_ * E_; i += 256) {
        int c = i >> 5, e = i & 31;
        w_s[i] = q_w[e * C_ + c];
    }
    {
        int c = tid;
        int g = c >> 3;
        float mu = g_mu_y[b * NGRP + g];
        float r  = g_rs_y[b * NGRP + g];
        float sc = r * gn_y_w[c];
        sy_s[c] = sc;
        ty_s[c] = gn_y_b[c] - mu * sc;
    }
    for (int i = tid; i < E_ * HALO * HALO; i += 256) {
        int e  = i / (HALO * HALO);
        int j  = i - e * (HALO * HALO);
        int jy = j / HALO, jx = j - jy * HALO;
        int gy = th0 - 2 + jy, gx = tw0 - 2 + jx;
        float v = 0.f;
        if (gy >= 0 && gy < HLO && gx >= 0 && gx < WLO)
            v = g_k[((size_t)(b * E_ + e) << 12) + (gy << 6) + gx];
        k_s[i] = v;
    }
    __syncthreads();

    // ---- phase b: q projection for this thread's hi-res pixel ----
    int oy  = tid >> 4, ox = tid & 15;             // 16x16 hi tile
    int gy2 = th0 * 2 + oy, gx2 = tw0 * 2 + ox;    // global hi-res coords
    const float* yp = y + (size_t)b * C_ * NPIX_HI + (gy2 << 7) + gx2;

    float qa[E_];
#pragma unroll
    for (int e = 0; e < E_; e++) qa[e] = __ldg(&q_b[e]);

#pragma unroll 2
    for (int c = 0; c < C_; c++) {
        float yv = yp[(size_t)c * NPIX_HI];
        float yn = fmaf(yv, sy_s[c], ty_s[c]);
        const float* wc = &w_s[c << 5];
#pragma unroll
        for (int e = 0; e < E_; e++) qa[e] = fmaf(wc[e], yn, qa[e]);
    }

    // ---- phase c: 25 logits against k halo tile ----
    int lh = oy >> 1, lw = ox >> 1;                // low-res position in tile
    float att[25];
    float mx = -1e30f;
#pragma unroll
    for (int o = 0; o < 25; o++) {
        int dy = o / 5, dx = o - dy * 5;
        const float* kp = &k_s[(lh + dy) * HALO + (lw + dx)];
        float s = 0.f;
#pragma unroll
        for (int e = 0; e < E_; e++) s = fmaf(qa[e], kp[e * (HALO * HALO)], s);
        att[o] = s;
        mx = fmaxf(mx, s);
    }

    // ---- phase d: softmax over 25 (registers) ----
    float den = 0.f;
#pragma unroll
    for (int o = 0; o < 25; o++) { float p = __expf(att[o] - mx); att[o] = p; den += p; }
    float inv = 1.f / den;
#pragma unroll
    for (int o = 0; o < 25; o++) att[o] *= inv;

    // ---- phase e: aggregation, 4 channels per chunk via float4 x tile ----
    const float* xb = x + (size_t)b * C_ * NPIX_LO;
    float* ob = out + (size_t)b * C_ * NPIX_HI + (gy2 << 7) + gx2;
    float4* x4 = reinterpret_cast<float4*>(x_s);

    for (int c0 = 0; c0 < C_; c0 += 4) {
        __syncthreads();   // also guards first-iteration w_s -> x_s reuse
        for (int i = tid; i < 4 * HALO * HALO; i += 256) {
            int k = i / (HALO * HALO);
            int j = i - k * (HALO * HALO);
            int jy = j / HALO, jx = j - jy * HALO;
            int gy = th0 - 2 + jy, gx = tw0 - 2 + jx;
            float v = 0.f;
            if (gy >= 0 && gy < HLO && gx >= 0 && gx < WLO)
                v = xb[(size_t)(c0 + k) * NPIX_LO + (gy << 6) + gx];
            x_s[(j << 2) + k] = v;
        }
        __syncthreads();

        float a0 = 0.f, a1 = 0.f, a2 = 0.f, a3 = 0.f;
#pragma unroll
        for (int o = 0; o < 25; o++) {
            int dy = o / 5, dx = o - dy * 5;
            float4 xv = x4[(lh + dy) * HALO + (lw + dx)];
            float w = att[o];
            a0 = fmaf(w, xv.x, a0);
            a1 = fmaf(w, xv.y, a1);
            a2 = fmaf(w, xv.z, a2);
            a3 = fmaf(w, xv.w, a3);
        }
        ob[(size_t)(c0 + 0) * NPIX_HI] = a0;
        ob[(size_t)(c0 + 1) * NPIX_HI] = a1;
        ob[(size_t)(c0 + 2) * NPIX_HI] = a2;
        ob[(size_t)(c0 + 3) * NPIX_HI] = a3;
    }
}

// ============================================================
extern "C" void kernel_launch(void* const* d_in, const int* in_sizes, int n_in,
                              void* d_out, int out_size)
{
    (void)in_sizes; (void)n_in; (void)out_size;
    const float* y      = (const float*)d_in[0];
    const float* x      = (const float*)d_in[1];
    const float* gn_y_w = (const float*)d_in[2];
    const float* gn_y_b = (const float*)d_in[3];
    const float* gn_x_w = (const float*)d_in[4];
    const float* gn_x_b = (const float*)d_in[5];
    const float* q_w    = (const float*)d_in[6];
    const float* q_b    = (const float*)d_in[7];
    const float* k_w    = (const float*)d_in[8];
    const float* k_b    = (const float*)d_in[9];
    float* out = (float*)d_out;

    void *mu_y, *rs_y, *mu_x, *rs_x;
    cudaGetSymbolAddress(&mu_y, g_mu_y);
    cudaGetSymbolAddress(&rs_y, g_rs_y);
    cudaGetSymbolAddress(&mu_x, g_mu_x);
    cudaGetSymbolAddress(&rs_x, g_rs_x);

    // GN stats: y groups are contiguous 8*16384 floats, x groups 8*4096.
    gn_stats_kernel<<<B_ * NGRP, 256>>>(y, CPG * NPIX_HI, (float*)mu_y, (float*)rs_y);
    gn_stats_kernel<<<B_ * NGRP, 256>>>(x, CPG * NPIX_LO, (float*)mu_x, (float*)rs_x);

    kproj_kernel<<<dim3(NPIX_LO / 256, B_), 256>>>(x, k_w, k_b, gn_x_w, gn_x_b);

    static const size_t smem_bytes = (8192 + 256 + 256 + E_ * HALO * HALO) * sizeof(float); // 53248
    cudaFuncSetAttribute(sapa_main_kernel,
                         cudaFuncAttributeMaxDynamicSharedMemorySize, (int)smem_bytes);
    sapa_main_kernel<<<dim3(WLO / TL, HLO / TL, B_), 256, smem_bytes>>>(
        y, q_w, q_b, gn_y_w, gn_y_b, x, out);
}

// round 2
// speedup vs baseline: 1.6848x; 1.6848x over previous
#include <cuda_runtime.h>
#include <cuda_bf16.h>
#include <cstddef>

// SAPA fused pipeline, fp32 with packed f32x2 FMA.
// Shapes: B=4, C=256, E=32, H=W=64, UP=2 (hi 128x128), K=5 (pad 2), GROUPS=32.

#define B_      4
#define C_      256
#define E_      32
#define HLO     64
#define WLO     64
#define NPIX_LO 4096
#define NPIX_HI 16384
#define NGRP    32
#define CPG     8
#define TL      8
#define HALO    12        // TL + 4
#define KSTRIDE 36        // padded e-stride per spatial point in k_s (16B aligned)
#define EPSF    1e-5f

typedef unsigned long long ull;

// ---------------- f32x2 helpers ----------------
#define FMA2(d, a, b, c) \
    asm("fma.rn.f32x2 %0, %1, %2, %3;" : "=l"(d) : "l"(a), "l"(b), "l"(c))

__device__ __forceinline__ ull pack2(float lo, float hi) {
    ull r; asm("mov.b64 %0, {%1, %2};" : "=l"(r) : "f"(lo), "f"(hi)); return r;
}
__device__ __forceinline__ ull dup2(float v) { return pack2(v, v); }
__device__ __forceinline__ void unpack2(float& lo, float& hi, ull d) {
    asm("mov.b64 {%0, %1}, %2;" : "=f"(lo), "=f"(hi) : "l"(d));
}

// ---------------- device scratch ----------------
__device__ float g_mu_y[B_ * NGRP];
__device__ float g_rs_y[B_ * NGRP];
__device__ float g_mu_x[B_ * NGRP];
__device__ float g_rs_x[B_ * NGRP];
__device__ float g_qwT[C_ * E_];               // q_w transposed [c][e]
__device__ float g_kwT[C_ * E_];               // k_w transposed [c][e]
__device__ float g_k[B_ * E_ * NPIX_LO];       // k features [b][e][pix]
__device__ float g_attn[B_ * 25 * NPIX_HI];    // attn [b][o][pix_hi]

// ============================================================
// Kernel 0: transpose weights to [c][e]
// ============================================================
__global__ void transpose_w_kernel(const float* __restrict__ qw,
                                   const float* __restrict__ kw)
{
    int i = blockIdx.x * 256 + threadIdx.x;   // 0 .. 8191
    int c = i >> 5, e = i & 31;
    g_qwT[i] = qw[e * C_ + c];
    g_kwT[i] = kw[e * C_ + c];
}

// ============================================================
// Kernel 1: per-(b,group) mean / rstd. One block per group.
// ============================================================
__global__ void gn_stats_kernel(const float* __restrict__ in, int n_per_group,
                                float* __restrict__ mu_out, float* __restrict__ rs_out)
{
    int bg  = blockIdx.x;
    int tid = threadIdx.x;
    const float4* p = reinterpret_cast<const float4*>(in + (size_t)bg * n_per_group);
    int n4 = n_per_group >> 2;

    float s = 0.f, ss = 0.f;
    for (int i = tid; i < n4; i += blockDim.x) {
        float4 v = p[i];
        s  += v.x + v.y + v.z + v.w;
        ss += v.x*v.x + v.y*v.y + v.z*v.z + v.w*v.w;
    }

    __shared__ float red_s[512];
    __shared__ float red_ss[512];
    red_s[tid] = s; red_ss[tid] = ss;
    __syncthreads();
    for (int off = blockDim.x >> 1; off > 0; off >>= 1) {
        if (tid < off) {
            red_s[tid]  += red_s[tid + off];
            red_ss[tid] += red_ss[tid + off];
        }
        __syncthreads();
    }
    if (tid == 0) {
        float inv_n = 1.f / (float)n_per_group;
        float m   = red_s[0] * inv_n;
        float var = red_ss[0] * inv_n - m * m;
        mu_out[bg] = m;
        rs_out[bg] = rsqrtf(var + EPSF);
    }
}

// ============================================================
// Kernel 2: k = k_w @ gn(x) + k_b.  4-way c-split, smem reduce.
// grid (64, 4) block 256: 64 pixels x 4 c-slices per block.
// ============================================================
__global__ void __launch_bounds__(256)
kproj_kernel(const float* __restrict__ x,
             const float* __restrict__ k_b,
             const float* __restrict__ gn_x_w,
             const float* __restrict__ gn_x_b)
{
    __shared__ float sm[8448 + 512];           // [0,8448): w_s then r_s; s/t after
    float* w_s = sm;                           // [c][e], 8192 used
    float* r_s = sm;                           // reduction, 256*33 = 8448
    float* s_s = sm + 8448;
    float* t_s = sm + 8704;

    int tid   = threadIdx.x;
    int b     = blockIdx.y;
    int slice = tid >> 6;
    int p     = tid & 63;
    int pix   = blockIdx.x * 64 + p;

    for (int i = tid; i < C_ * E_; i += 256) w_s[i] = g_kwT[i];
    {
        int c = tid;
        int g = c >> 3;
        float mu = g_mu_x[b * NGRP + g];
        float r  = g_rs_x[b * NGRP + g];
        float sc = r * gn_x_w[c];
        s_s[c] = sc;
        t_s[c] = gn_x_b[c] - mu * sc;
    }
    __syncthreads();

    const float* xp = x + (size_t)b * C_ * NPIX_LO + pix;
    const ulonglong2* w2 = reinterpret_cast<const ulonglong2*>(w_s);
    const float4* s4 = reinterpret_cast<const float4*>(s_s);
    const float4* t4 = reinterpret_cast<const float4*>(t_s);

    ull qa2[16];
#pragma unroll
    for (int j = 0; j < 16; j++) qa2[j] = 0ull;

    int cbase = slice * 64;
#pragma unroll 2
    for (int c0 = cbase; c0 < cbase + 64; c0 += 4) {
        float xv0 = xp[(size_t)(c0 + 0) * NPIX_LO];
        float xv1 = xp[(size_t)(c0 + 1) * NPIX_LO];
        float xv2 = xp[(size_t)(c0 + 2) * NPIX_LO];
        float xv3 = xp[(size_t)(c0 + 3) * NPIX_LO];
        float4 sc = s4[c0 >> 2], tc = t4[c0 >> 2];
        ull yn0 = dup2(fmaf(xv0, sc.x, tc.x));
        ull yn1 = dup2(fmaf(xv1, sc.y, tc.y));
        ull yn2 = dup2(fmaf(xv2, sc.z, tc.z));
        ull yn3 = dup2(fmaf(xv3, sc.w, tc.w));
#pragma unroll
        for (int j = 0; j < 8; j++) {
            ulonglong2 w0 = w2[(c0 + 0) * 8 + j];
            FMA2(qa2[2*j],   w0.x, yn0, qa2[2*j]);
            FMA2(qa2[2*j+1], w0.y, yn0, qa2[2*j+1]);
            ulonglong2 w1 = w2[(c0 + 1) * 8 + j];
            FMA2(qa2[2*j],   w1.x, yn1, qa2[2*j]);
            FMA2(qa2[2*j+1], w1.y, yn1, qa2[2*j+1]);
            ulonglong2 wv2 = w2[(c0 + 2) * 8 + j];
            FMA2(qa2[2*j],   wv2.x, yn2, qa2[2*j]);
            FMA2(qa2[2*j+1], wv2.y, yn2, qa2[2*j+1]);
            ulonglong2 w3 = w2[(c0 + 3) * 8 + j];
            FMA2(qa2[2*j],   w3.x, yn3, qa2[2*j]);
            FMA2(qa2[2*j+1], w3.y, yn3, qa2[2*j+1]);
        }
    }

    __syncthreads();   // w_s dead, reuse as r_s
#pragma unroll
    for (int j = 0; j < 16; j++) {
        float lo, hi; unpack2(lo, hi, qa2[j]);
        r_s[tid * 33 + 2*j]     = lo;
        r_s[tid * 33 + 2*j + 1] = hi;
    }
    __syncthreads();

    // final: thread t = (pixel p2 = t&63, e-octet q = t>>6)
    int q  = tid >> 6;
    int p2 = tid & 63;
    float acc[8];
#pragma unroll
    for (int j = 0; j < 8; j++) acc[j] = __ldg(&k_b[q * 8 + j]);
#pragma unroll
    for (int s = 0; s < 4; s++) {
        const float* rp = &r_s[(s * 64 + p2) * 33 + q * 8];
#pragma unroll
        for (int j = 0; j < 8; j++) acc[j] += rp[j];
    }
    int pix2 = blockIdx.x * 64 + p2;
#pragma unroll
    for (int j = 0; j < 8; j++)
        g_k[((size_t)(b * E_ + q * 8 + j) << 12) + pix2] = acc[j];
}

// ============================================================
// Kernel 3: q-proj (GN folded) + 25 logits + softmax -> g_attn
// grid (8, 8, 4) block 256; thread = one hi-res pixel of 16x16 tile.
// smem floats: w_s 8192 | sy 256 | ty 256 | k_s 144*36=5184
// ============================================================
__global__ void __launch_bounds__(256)
sapa_attn_kernel(const float* __restrict__ y,
                 const float* __restrict__ q_b,
                 const float* __restrict__ gn_y_w,
                 const float* __restrict__ gn_y_b)
{
    extern __shared__ float smA[];
    float* w_s  = smA;
    float* sy_s = smA + 8192;
    float* ty_s = smA + 8448;
    float* k_s  = smA + 8704;

    int tid = threadIdx.x;
    int b   = blockIdx.z;
    int th0 = blockIdx.y * TL;
    int tw0 = blockIdx.x * TL;

    for (int i = tid; i < C_ * E_; i += 256) w_s[i] = g_qwT[i];
    {
        int c = tid;
        int g = c >> 3;
        float mu = g_mu_y[b * NGRP + g];
        float r  = g_rs_y[b * NGRP + g];
        float sc = r * gn_y_w[c];
        sy_s[c] = sc;
        ty_s[c] = gn_y_b[c] - mu * sc;
    }
    for (int i = tid; i < E_ * HALO * HALO; i += 256) {
        int e  = i / (HALO * HALO);
        int j  = i - e * (HALO * HALO);
        int jy = j / HALO, jx = j - jy * HALO;
        int gy = th0 - 2 + jy, gx = tw0 - 2 + jx;
        float v = 0.f;
        if (gy >= 0 && gy < HLO && gx >= 0 && gx < WLO)
            v = g_k[((size_t)(b * E_ + e) << 12) + (gy << 6) + gx];
        k_s[j * KSTRIDE + e] = v;
    }
    __syncthreads();

    int oy  = tid >> 4, ox = tid & 15;
    int gy2 = th0 * 2 + oy, gx2 = tw0 * 2 + ox;
    const float* yp = y + (size_t)b * C_ * NPIX_HI + (gy2 << 7) + gx2;
    const ulonglong2* w2 = reinterpret_cast<const ulonglong2*>(w_s);
    const float4* sy4 = reinterpret_cast<const float4*>(sy_s);
    const float4* ty4 = reinterpret_cast<const float4*>(ty_s);

    ull qa2[16];
#pragma unroll
    for (int j = 0; j < 16; j++)
        qa2[j] = pack2(__ldg(&q_b[2*j]), __ldg(&q_b[2*j + 1]));

#pragma unroll 2
    for (int c0 = 0; c0 < C_; c0 += 4) {
        float yv0 = yp[(size_t)(c0 + 0) * NPIX_HI];
        float yv1 = yp[(size_t)(c0 + 1) * NPIX_HI];
        float yv2 = yp[(size_t)(c0 + 2) * NPIX_HI];
        float yv3 = yp[(size_t)(c0 + 3) * NPIX_HI];
        float4 sc = sy4[c0 >> 2], tc = ty4[c0 >> 2];
        ull yn0 = dup2(fmaf(yv0, sc.x, tc.x));
        ull yn1 = dup2(fmaf(yv1, sc.y, tc.y));
        ull yn2 = dup2(fmaf(yv2, sc.z, tc.z));
        ull yn3 = dup2(fmaf(yv3, sc.w, tc.w));
#pragma unroll
        for (int j = 0; j < 8; j++) {
            ulonglong2 w0 = w2[(c0 + 0) * 8 + j];
            FMA2(qa2[2*j],   w0.x, yn0, qa2[2*j]);
            FMA2(qa2[2*j+1], w0.y, yn0, qa2[2*j+1]);
            ulonglong2 w1 = w2[(c0 + 1) * 8 + j];
            FMA2(qa2[2*j],   w1.x, yn1, qa2[2*j]);
            FMA2(qa2[2*j+1], w1.y, yn1, qa2[2*j+1]);
            ulonglong2 wv2 = w2[(c0 + 2) * 8 + j];
            FMA2(qa2[2*j],   wv2.x, yn2, qa2[2*j]);
            FMA2(qa2[2*j+1], wv2.y, yn2, qa2[2*j+1]);
            ulonglong2 w3 = w2[(c0 + 3) * 8 + j];
            FMA2(qa2[2*j],   w3.x, yn3, qa2[2*j]);
            FMA2(qa2[2*j+1], w3.y, yn3, qa2[2*j+1]);
        }
    }

    // logits
    int lh = oy >> 1, lw = ox >> 1;
    float att[25];
    float mx = -1e30f;
#pragma unroll
    for (int o = 0; o < 25; o++) {
        int dy = o / 5, dx = o - dy * 5;
        const ulonglong2* kp = reinterpret_cast<const ulonglong2*>(
            &k_s[((lh + dy) * HALO + (lw + dx)) * KSTRIDE]);
        ull sa = 0ull, sb = 0ull;
#pragma unroll
        for (int j = 0; j < 8; j++) {
            ulonglong2 kv = kp[j];
            FMA2(sa, qa2[2*j],   kv.x, sa);
            FMA2(sb, qa2[2*j+1], kv.y, sb);
        }
        float a0, a1, b0, b1;
        unpack2(a0, a1, sa);
        unpack2(b0, b1, sb);
        float lg = (a0 + a1) + (b0 + b1);
        att[o] = lg;
        mx = fmaxf(mx, lg);
    }

    float den = 0.f;
#pragma unroll
    for (int o = 0; o < 25; o++) { float pz = __expf(att[o] - mx); att[o] = pz; den += pz; }
    float inv = 1.f / den;

    int pixhi = (gy2 << 7) + gx2;
#pragma unroll
    for (int o = 0; o < 25; o++)
        g_attn[((size_t)(b * 25 + o) << 14) + pixhi] = att[o] * inv;
}

// ============================================================
// Kernel 4: aggregation.  grid (64 tiles, 8 chan-groups, 4 b), block 256.
// Each block: 16x16 hi tile x 32 channels (4 chunks of 8).
// ============================================================
__global__ void __launch_bounds__(256)
sapa_agg_kernel(const float* __restrict__ x, float* __restrict__ out)
{
    __shared__ float x_s[HALO * HALO * 12];    // [spat][ch(8, stride 12)]

    int tid = threadIdx.x;
    int b   = blockIdx.z;
    int th0 = (blockIdx.x >> 3) * TL;
    int tw0 = (blockIdx.x & 7) * TL;
    int cb  = blockIdx.y * 32;

    int oy  = tid >> 4, ox = tid & 15;
    int gy2 = th0 * 2 + oy, gx2 = tw0 * 2 + ox;
    int pixhi = (gy2 << 7) + gx2;
    int lh = oy >> 1, lw = ox >> 1;

    float att[25];
#pragma unroll
    for (int o = 0; o < 25; o++)
        att[o] = g_attn[((size_t)(b * 25 + o) << 14) + pixhi];

    const float* xb = x + (size_t)b * C_ * NPIX_LO;
    float* ob = out + (size_t)b * C_ * NPIX_HI + pixhi;

    for (int cg = 0; cg < 4; cg++) {
        int c0 = cb + cg * 8;
        __syncthreads();
        for (int i = tid; i < 8 * HALO * HALO; i += 256) {
            int ch = i / (HALO * HALO);
            int j  = i - ch * (HALO * HALO);
            int jy = j / HALO, jx = j - jy * HALO;
            int gy = th0 - 2 + jy, gx = tw0 - 2 + jx;
            float v = 0.f;
            if (gy >= 0 && gy < HLO && gx >= 0 && gx < WLO)
                v = xb[(size_t)(c0 + ch) * NPIX_LO + (gy << 6) + gx];
            x_s[j * 12 + ch] = v;
        }
        __syncthreads();

        ull a2[4];
#pragma unroll
        for (int j = 0; j < 4; j++) a2[j] = 0ull;
#pragma unroll
        for (int o = 0; o < 25; o++) {
            int dy = o / 5, dx = o - dy * 5;
            const ulonglong2* xp = reinterpret_cast<const ulonglong2*>(
                &x_s[((lh + dy) * HALO + (lw + dx)) * 12]);
            ull w = dup2(att[o]);
            ulonglong2 v0 = xp[0];
            ulonglong2 v1 = xp[1];
            FMA2(a2[0], w, v0.x, a2[0]);
            FMA2(a2[1], w, v0.y, a2[1]);
            FMA2(a2[2], w, v1.x, a2[2]);
            FMA2(a2[3], w, v1.y, a2[3]);
        }
#pragma unroll
        for (int j = 0; j < 4; j++) {
            float lo, hi; unpack2(lo, hi, a2[j]);
            ob[(size_t)(c0 + 2*j)     * NPIX_HI] = lo;
            ob[(size_t)(c0 + 2*j + 1) * NPIX_HI] = hi;
        }
    }
}

// ============================================================
extern "C" void kernel_launch(void* const* d_in, const int* in_sizes, int n_in,
                              void* d_out, int out_size)
{
    (void)in_sizes; (void)n_in; (void)out_size;
    const float* y      = (const float*)d_in[0];
    const float* x      = (const float*)d_in[1];
    const float* gn_y_w = (const float*)d_in[2];
    const float* gn_y_b = (const float*)d_in[3];
    const float* gn_x_w = (const float*)d_in[4];
    const float* gn_x_b = (const float*)d_in[5];
    const float* q_w    = (const float*)d_in[6];
    const float* q_b    = (const float*)d_in[7];
    const float* k_w    = (const float*)d_in[8];
    const float* k_b    = (const float*)d_in[9];
    float* out = (float*)d_out;

    void *mu_y, *rs_y, *mu_x, *rs_x;
    cudaGetSymbolAddress(&mu_y, g_mu_y);
    cudaGetSymbolAddress(&rs_y, g_rs_y);
    cudaGetSymbolAddress(&mu_x, g_mu_x);
    cudaGetSymbolAddress(&rs_x, g_rs_x);

    transpose_w_kernel<<<32, 256>>>(q_w, k_w);

    gn_stats_kernel<<<B_ * NGRP, 512>>>(y, CPG * NPIX_HI, (float*)mu_y, (float*)rs_y);
    gn_stats_kernel<<<B_ * NGRP, 512>>>(x, CPG * NPIX_LO, (float*)mu_x, (float*)rs_x);

    kproj_kernel<<<dim3(NPIX_LO / 64, B_), 256>>>(x, k_b, gn_x_w, gn_x_b);

    static const size_t smemA = (8192 + 256 + 256 + HALO * HALO * KSTRIDE) * sizeof(float);
    cudaFuncSetAttribute(sapa_attn_kernel,
                         cudaFuncAttributeMaxDynamicSharedMemorySize, (int)smemA);
    sapa_attn_kernel<<<dim3(WLO / TL, HLO / TL, B_), 256, smemA>>>(y, q_b, gn_y_w, gn_y_b);

    sapa_agg_kernel<<<dim3(64, 8, B_), 256>>>(x, out);
}